// round 14
// baseline (speedup 1.0000x reference)
#include <cuda_runtime.h>
#include <math.h>

#define M_ROWS 512
#define K_COMP 8
#define B_PTS  4096
#define B_QTR  1024
#define PHI_DIM 120
#define Z_COLS 80
#define LOG2PI_F 1.8378770664093453f
#define LOG2E_F  1.4426950408889634f

#define NBLK   444              // 148 SMs x 3 CTAs, residency via launch_bounds
#define NITEM  2048             // 512 m x 4 quarters

// Scratch (device globals — no allocation allowed)
__device__ float g_zT[72][M_ROWS];            // z cols 0..71, column-major
__device__ float g_respT[4][K_COMP][M_ROWS];  // per-quarter resp partials
__device__ unsigned g_arrive, g_done;

typedef unsigned long long u64;

__device__ __forceinline__ float ex2f(float x) {
    float r; asm("ex2.approx.f32 %0, %1;" : "=f"(r) : "f"(x)); return r;
}
__device__ __forceinline__ float rcpf(float x) {
    float r; asm("rcp.approx.f32 %0, %1;" : "=f"(r) : "f"(x)); return r;
}
__device__ __forceinline__ u64 pk2(float lo, float hi) {
    u64 r; asm("mov.b64 %0, {%1, %2};" : "=l"(r) : "f"(lo), "f"(hi)); return r;
}
__device__ __forceinline__ void unpk2(u64 v, float& lo, float& hi) {
    asm("mov.b64 {%0, %1}, %2;" : "=f"(lo), "=f"(hi) : "l"(v));
}
__device__ __forceinline__ u64 fma2(u64 a, u64 b, u64 c) {
    u64 d; asm("fma.rn.f32x2 %0, %1, %2, %3;" : "=l"(d) : "l"(a), "l"(b), "l"(c)); return d;
}

// ---------------------------------------------------------------------------
// One persistent kernel: static-stride (m,quarter) items -> grid barrier -> norm.
// ---------------------------------------------------------------------------
__global__ void __launch_bounds__(128, 3) gmm_all(const float* __restrict__ phi,
                                                  const float4* __restrict__ X,
                                                  float* __restrict__ out) {
    const int tid = threadIdx.x;
    const unsigned lane = tid & 31;
    const unsigned wid = tid >> 5;

    // Per k: A (lower-tri, 10), b0..b3, nck2 (= -ck*log2e)
    __shared__ float sp[K_COMP][15];
    __shared__ float sred[4][K_COMP];

    // ===================== PHASE 1: static-stride items ======================
    for (int item = blockIdx.x; item < NITEM; item += NBLK) {
        const int m = item >> 2;
        const int q = item & 3;

        // ---- prep: threads 0..7, one k each ----
        if (tid < K_COMP) {
            const int k = tid;
            const float* pm = phi + m * PHI_DIM;

            float mx = -INFINITY;
            #pragma unroll
            for (int j = 0; j < K_COMP; j++) mx = fmaxf(mx, pm[j]);
            float s = 0.f;
            #pragma unroll
            for (int j = 0; j < K_COMP; j++) s += __expf(pm[j] - mx);
            float pik = __expf(pm[k] - mx) / s;

            float mu0 = pm[8 + k * 4 + 0];
            float mu1 = pm[8 + k * 4 + 1];
            float mu2 = pm[8 + k * 4 + 2];
            float mu3 = pm[8 + k * 4 + 3];

            const float* lv = pm + 40 + k * 10;
            float L00 = lv[0], L10 = lv[1], L11 = lv[2], L20 = lv[3], L21 = lv[4];
            float L22 = lv[5], L30 = lv[6], L31 = lv[7], L32 = lv[8], L33 = lv[9];

            float G00 = 1.0f / L00, G11 = 1.0f / L11, G22 = 1.0f / L22, G33 = 1.0f / L33;
            float G10 = -L10 * G00 * G11;
            float G21 = -L21 * G11 * G22;
            float G20 = -(L20 * G00 + L21 * G10) * G22;
            float G32 = -L32 * G22 * G33;
            float G31 = -(L31 * G11 + L32 * G21) * G33;
            float G30 = -(L30 * G00 + L31 * G10 + L32 * G20) * G33;

            const float sc = sqrtf(0.5f * LOG2E_F);   // |a|^2 in log2 units
            float A00 = sc * G00, A10 = sc * G10, A11 = sc * G11;
            float A20 = sc * G20, A21 = sc * G21, A22 = sc * G22;
            float A30 = sc * G30, A31 = sc * G31, A32 = sc * G32, A33 = sc * G33;

            sp[k][0] = A00; sp[k][1] = A10; sp[k][2] = A11; sp[k][3] = A20;
            sp[k][4] = A21; sp[k][5] = A22; sp[k][6] = A30; sp[k][7] = A31;
            sp[k][8] = A32; sp[k][9] = A33;
            sp[k][10] = -(A00 * mu0);
            sp[k][11] = -(A10 * mu0 + A11 * mu1);
            sp[k][12] = -(A20 * mu0 + A21 * mu1 + A22 * mu2);
            sp[k][13] = -(A30 * mu0 + A31 * mu1 + A32 * mu2 + A33 * mu3);

            float log_det = 2.0f * (__logf(fmaxf(fabsf(L00), 1e-8f)) +
                                    __logf(fmaxf(fabsf(L11), 1e-8f)) +
                                    __logf(fmaxf(fabsf(L22), 1e-8f)) +
                                    __logf(fmaxf(fabsf(L33), 1e-8f)));
            float ckv = __logf(fmaxf(pik, 1e-8f)) - 0.5f * (4.0f * LOG2PI_F + log_det);
            sp[k][14] = -(ckv * LOG2E_F);             // nck2

            if (q == 0) {
                g_zT[k * 4 + 0][m] = mu0;
                g_zT[k * 4 + 1][m] = mu1;
                g_zT[k * 4 + 2][m] = mu2;
                g_zT[k * 4 + 3][m] = mu3;
                g_zT[32 + k * 4 + 0][m] = __logf(fmaxf(fabsf(L00), 1e-6f));
                g_zT[32 + k * 4 + 1][m] = __logf(fmaxf(fabsf(L11), 1e-6f));
                g_zT[32 + k * 4 + 2][m] = __logf(fmaxf(fabsf(L22), 1e-6f));
                g_zT[32 + k * 4 + 3][m] = __logf(fmaxf(fabsf(L33), 1e-6f));
                g_zT[64 + k][m] = pik;
            }
        }
        __syncthreads();

        // ---- pack params into k-pair u64 registers (same 120 regs as scalar)
        u64 A00[4], A10[4], A11[4], A20[4], A21[4];
        u64 A22[4], A30[4], A31[4], A32[4], A33[4];
        u64 B0[4], B1[4], B2[4], B3[4], NCK[4];
        #pragma unroll
        for (int p = 0; p < 4; p++) {
            const float* a = sp[2 * p];
            const float* b = sp[2 * p + 1];
            A00[p] = pk2(a[0], b[0]);  A10[p] = pk2(a[1], b[1]);
            A11[p] = pk2(a[2], b[2]);  A20[p] = pk2(a[3], b[3]);
            A21[p] = pk2(a[4], b[4]);  A22[p] = pk2(a[5], b[5]);
            A30[p] = pk2(a[6], b[6]);  A31[p] = pk2(a[7], b[7]);
            A32[p] = pk2(a[8], b[8]);  A33[p] = pk2(a[9], b[9]);
            B0[p]  = pk2(a[10], b[10]); B1[p] = pk2(a[11], b[11]);
            B2[p]  = pk2(a[12], b[12]); B3[p] = pk2(a[13], b[13]);
            NCK[p] = pk2(a[14], b[14]);
        }

        float acc[K_COMP];
        #pragma unroll
        for (int k = 0; k < K_COMP; k++) acc[k] = 0.f;

        const int pbase = q * B_QTR + tid;
        #pragma unroll 2
        for (int it = 0; it < 8; it++) {
            float4 x = X[pbase + it * 128];
            u64 xp0 = pk2(x.x, x.x);
            u64 xp1 = pk2(x.y, x.y);
            u64 xp2 = pk2(x.z, x.z);
            u64 xp3 = pk2(x.w, x.w);

            float qv[K_COMP];
            #pragma unroll
            for (int p = 0; p < 4; p++) {
                u64 a0 = fma2(xp0, A00[p], B0[p]);
                u64 a1 = fma2(xp1, A11[p], B1[p]);
                a1 = fma2(xp0, A10[p], a1);
                u64 a2 = fma2(xp2, A22[p], B2[p]);
                a2 = fma2(xp1, A21[p], a2);
                a2 = fma2(xp0, A20[p], a2);
                u64 a3 = fma2(xp3, A33[p], B3[p]);
                a3 = fma2(xp2, A32[p], a3);
                a3 = fma2(xp1, A31[p], a3);
                a3 = fma2(xp0, A30[p], a3);
                u64 qq = fma2(a3, a3, NCK[p]);
                qq = fma2(a2, a2, qq);
                qq = fma2(a1, a1, qq);
                qq = fma2(a0, a0, qq);
                unpk2(qq, qv[2 * p], qv[2 * p + 1]);
            }
            float mn = fminf(fminf(fminf(qv[0], qv[1]), fminf(qv[2], qv[3])),
                             fminf(fminf(qv[4], qv[5]), fminf(qv[6], qv[7])));
            float ex[K_COMP];
            #pragma unroll
            for (int k = 0; k < K_COMP; k++) ex[k] = ex2f(mn - qv[k]);
            float s = ((ex[0] + ex[1]) + (ex[2] + ex[3])) +
                      ((ex[4] + ex[5]) + (ex[6] + ex[7]));
            float inv = rcpf(s);                       // s >= 1, safe
            #pragma unroll
            for (int k = 0; k < K_COMP; k++) acc[k] = __fmaf_rn(ex[k], inv, acc[k]);
        }

        // ---- block reduce (4 warps) ----
        #pragma unroll
        for (int k = 0; k < K_COMP; k++) {
            float v = acc[k];
            v += __shfl_down_sync(0xffffffffu, v, 16);
            v += __shfl_down_sync(0xffffffffu, v, 8);
            v += __shfl_down_sync(0xffffffffu, v, 4);
            v += __shfl_down_sync(0xffffffffu, v, 2);
            v += __shfl_down_sync(0xffffffffu, v, 1);
            if (lane == 0) sred[wid][k] = v;
        }
        __syncthreads();
        if (tid < K_COMP) {
            g_respT[q][tid][m] = sred[0][tid] + sred[1][tid] +
                                 sred[2][tid] + sred[3][tid];
        }
        __syncthreads();   // protect sp/sred reuse next item
    }

    // ===================== grid barrier (all 444 resident) ====================
    __syncthreads();
    if (tid == 0) {
        __threadfence();
        atomicAdd(&g_arrive, 1u);
        volatile unsigned* p = &g_arrive;
        while (*p < NBLK) __nanosleep(64);
    }
    __syncthreads();
    __threadfence();

    // ===================== PHASE 2: standardization (blocks 0..79) ===========
    if (blockIdx.x < Z_COLS) {
        const int c = blockIdx.x;
        float v[4];
        if (c < 72) {
            const float* col = g_zT[c];
            #pragma unroll
            for (int j = 0; j < 4; j++) v[j] = col[tid + 128 * j];
        } else {
            const int k = c - 72;
            #pragma unroll
            for (int j = 0; j < 4; j++) {
                int r = tid + 128 * j;
                v[j] = (g_respT[0][k][r] + g_respT[1][k][r] +
                        g_respT[2][k][r] + g_respT[3][k][r]) * (1.0f / (float)B_PTS);
            }
        }

        __shared__ float nsh[4];
        __shared__ float n_mean, n_rstd;

        float s = (v[0] + v[1]) + (v[2] + v[3]);
        s += __shfl_down_sync(0xffffffffu, s, 16);
        s += __shfl_down_sync(0xffffffffu, s, 8);
        s += __shfl_down_sync(0xffffffffu, s, 4);
        s += __shfl_down_sync(0xffffffffu, s, 2);
        s += __shfl_down_sync(0xffffffffu, s, 1);
        if (lane == 0) nsh[wid] = s;
        __syncthreads();
        if (tid == 0) n_mean = (nsh[0] + nsh[1] + nsh[2] + nsh[3]) * (1.0f / (float)M_ROWS);
        __syncthreads();
        float mean = n_mean;

        float qsum = 0.f;
        #pragma unroll
        for (int j = 0; j < 4; j++) {
            v[j] -= mean;
            qsum = __fmaf_rn(v[j], v[j], qsum);
        }
        qsum += __shfl_down_sync(0xffffffffu, qsum, 16);
        qsum += __shfl_down_sync(0xffffffffu, qsum, 8);
        qsum += __shfl_down_sync(0xffffffffu, qsum, 4);
        qsum += __shfl_down_sync(0xffffffffu, qsum, 2);
        qsum += __shfl_down_sync(0xffffffffu, qsum, 1);
        __syncthreads();
        if (lane == 0) nsh[wid] = qsum;
        __syncthreads();
        if (tid == 0) {
            float var = (nsh[0] + nsh[1] + nsh[2] + nsh[3]) * (1.0f / (float)(M_ROWS - 1));
            n_rstd = 1.0f / fmaxf(sqrtf(var), 1e-6f);
        }
        __syncthreads();
        float rstd = n_rstd;
        #pragma unroll
        for (int j = 0; j < 4; j++) {
            int r = tid + 128 * j;
            out[r * Z_COLS + c] = v[j] * rstd;
        }
    }

    // ============== counter reset (state -> 0 for graph replay) ==============
    __syncthreads();
    if (tid == 0) {
        __threadfence();
        unsigned d = atomicAdd(&g_done, 1u);
        if (d == NBLK - 1) {
            g_arrive = 0u;
            g_done = 0u;
            __threadfence();
        }
    }
}

// ---------------------------------------------------------------------------
extern "C" void kernel_launch(void* const* d_in, const int* in_sizes, int n_in,
                              void* d_out, int out_size) {
    const float* phi = (const float*)d_in[0];
    const float4* X = (const float4*)d_in[1];
    float* out = (float*)d_out;

    gmm_all<<<NBLK, 128>>>(phi, X, out);
}

// round 15
// speedup vs baseline: 1.1383x; 1.1383x over previous
#include <cuda_runtime.h>
#include <math.h>

#define M_ROWS 512
#define K_COMP 8
#define B_PTS  4096
#define B_QTR  1024
#define PHI_DIM 120
#define Z_COLS 80
#define LOG2PI_F 1.8378770664093453f
#define LOG2E_F  1.4426950408889634f

#define NBLK   444              // 148 SMs x 3 CTAs, residency via launch_bounds
#define NITEM  2048             // 512 m x 4 quarters

// Scratch (device globals — no allocation allowed)
__device__ float4 g_par[M_ROWS][K_COMP][4];   // 16 floats per (m,k): A(10), b(4), nck2, pad
__device__ float g_zT[72][M_ROWS];            // z cols 0..71, column-major
__device__ float g_respT[4][K_COMP][M_ROWS];  // per-quarter resp partials
__device__ unsigned g_ticket, g_bar0, g_bar1, g_done;

__device__ __forceinline__ float ex2f(float x) {
    float r; asm("ex2.approx.f32 %0, %1;" : "=f"(r) : "f"(x)); return r;
}
__device__ __forceinline__ float rcpf(float x) {
    float r; asm("rcp.approx.f32 %0, %1;" : "=f"(r) : "f"(x)); return r;
}

__device__ __forceinline__ void grid_barrier(unsigned* ctr) {
    __syncthreads();
    if (threadIdx.x == 0) {
        __threadfence();
        atomicAdd(ctr, 1u);
        volatile unsigned* p = ctr;
        while (*p < NBLK) __nanosleep(64);
    }
    __syncthreads();
    __threadfence();
}

// ---------------------------------------------------------------------------
// One persistent kernel: phase-0 prep -> barrier -> ticketed quarters -> barrier -> norm.
// ---------------------------------------------------------------------------
__global__ void __launch_bounds__(128, 3) gmm_all(const float* __restrict__ phi,
                                                  const float4* __restrict__ X,
                                                  float* __restrict__ out) {
    const int tid = threadIdx.x;
    const unsigned lane = tid & 31;
    const unsigned wid = tid >> 5;

    __shared__ float sred[4][K_COMP];
    __shared__ unsigned s_item;

    // ===================== PHASE 0: prep (4096 (m,k) tasks) ==================
    {
        int gid = blockIdx.x * 128 + tid;
        if (gid < M_ROWS * K_COMP) {
            const int m = gid >> 3, k = gid & 7;
            const float* pm = phi + m * PHI_DIM;

            float mx = -INFINITY;
            #pragma unroll
            for (int j = 0; j < K_COMP; j++) mx = fmaxf(mx, pm[j]);
            float s = 0.f;
            #pragma unroll
            for (int j = 0; j < K_COMP; j++) s += __expf(pm[j] - mx);
            float pik = __expf(pm[k] - mx) / s;

            float mu0 = pm[8 + k * 4 + 0];
            float mu1 = pm[8 + k * 4 + 1];
            float mu2 = pm[8 + k * 4 + 2];
            float mu3 = pm[8 + k * 4 + 3];

            const float* lv = pm + 40 + k * 10;
            float L00 = lv[0], L10 = lv[1], L11 = lv[2], L20 = lv[3], L21 = lv[4];
            float L22 = lv[5], L30 = lv[6], L31 = lv[7], L32 = lv[8], L33 = lv[9];

            float G00 = 1.0f / L00, G11 = 1.0f / L11, G22 = 1.0f / L22, G33 = 1.0f / L33;
            float G10 = -L10 * G00 * G11;
            float G21 = -L21 * G11 * G22;
            float G20 = -(L20 * G00 + L21 * G10) * G22;
            float G32 = -L32 * G22 * G33;
            float G31 = -(L31 * G11 + L32 * G21) * G33;
            float G30 = -(L30 * G00 + L31 * G10 + L32 * G20) * G33;

            const float sc = sqrtf(0.5f * LOG2E_F);   // |a|^2 in log2 units
            float A00 = sc * G00, A10 = sc * G10, A11 = sc * G11;
            float A20 = sc * G20, A21 = sc * G21, A22 = sc * G22;
            float A30 = sc * G30, A31 = sc * G31, A32 = sc * G32, A33 = sc * G33;

            float b0 = -(A00 * mu0);
            float b1 = -(A10 * mu0 + A11 * mu1);
            float b2 = -(A20 * mu0 + A21 * mu1 + A22 * mu2);
            float b3 = -(A30 * mu0 + A31 * mu1 + A32 * mu2 + A33 * mu3);

            float log_det = 2.0f * (__logf(fmaxf(fabsf(L00), 1e-8f)) +
                                    __logf(fmaxf(fabsf(L11), 1e-8f)) +
                                    __logf(fmaxf(fabsf(L22), 1e-8f)) +
                                    __logf(fmaxf(fabsf(L33), 1e-8f)));
            float ckv = __logf(fmaxf(pik, 1e-8f)) - 0.5f * (4.0f * LOG2PI_F + log_det);
            float nck = -(ckv * LOG2E_F);

            g_par[m][k][0] = make_float4(A00, A10, A11, A20);
            g_par[m][k][1] = make_float4(A21, A22, A30, A31);
            g_par[m][k][2] = make_float4(A32, A33, b0, b1);
            g_par[m][k][3] = make_float4(b2, b3, nck, 0.f);

            g_zT[k * 4 + 0][m] = mu0;
            g_zT[k * 4 + 1][m] = mu1;
            g_zT[k * 4 + 2][m] = mu2;
            g_zT[k * 4 + 3][m] = mu3;
            g_zT[32 + k * 4 + 0][m] = __logf(fmaxf(fabsf(L00), 1e-6f));
            g_zT[32 + k * 4 + 1][m] = __logf(fmaxf(fabsf(L11), 1e-6f));
            g_zT[32 + k * 4 + 2][m] = __logf(fmaxf(fabsf(L22), 1e-6f));
            g_zT[32 + k * 4 + 3][m] = __logf(fmaxf(fabsf(L33), 1e-6f));
            g_zT[64 + k][m] = pik;
        }
    }

    grid_barrier(&g_bar0);

    // ===================== PHASE 1: block-ticketed quarter items =============
    for (;;) {
        if (tid == 0) s_item = atomicAdd(&g_ticket, 1u);
        __syncthreads();
        const unsigned item = s_item;
        if (item >= NITEM) break;
        const int m = item >> 2;
        const int q = item & 3;

        // ---- load params (broadcast LDG.128, L1/L2-hot) ----
        float A00[K_COMP], A10[K_COMP], A11[K_COMP], A20[K_COMP], A21[K_COMP];
        float A22[K_COMP], A30[K_COMP], A31[K_COMP], A32[K_COMP], A33[K_COMP];
        float b0[K_COMP], b1[K_COMP], b2[K_COMP], b3[K_COMP], nck[K_COMP];
        #pragma unroll
        for (int k = 0; k < K_COMP; k++) {
            float4 p0 = g_par[m][k][0];
            float4 p1 = g_par[m][k][1];
            float4 p2 = g_par[m][k][2];
            float4 p3 = g_par[m][k][3];
            A00[k] = p0.x; A10[k] = p0.y; A11[k] = p0.z; A20[k] = p0.w;
            A21[k] = p1.x; A22[k] = p1.y; A30[k] = p1.z; A31[k] = p1.w;
            A32[k] = p2.x; A33[k] = p2.y; b0[k] = p2.z;  b1[k] = p2.w;
            b2[k] = p3.x;  b3[k] = p3.y;  nck[k] = p3.z;
        }

        float acc[K_COMP];
        #pragma unroll
        for (int k = 0; k < K_COMP; k++) acc[k] = 0.f;

        const int pbase = q * B_QTR + tid;
        #pragma unroll 2
        for (int it = 0; it < 8; it++) {
            float4 x = X[pbase + it * 128];
            float qv[K_COMP];
            #pragma unroll
            for (int k = 0; k < K_COMP; k++) {
                float a0 = __fmaf_rn(x.x, A00[k], b0[k]);
                float a1 = __fmaf_rn(x.x, A10[k], __fmaf_rn(x.y, A11[k], b1[k]));
                float a2 = __fmaf_rn(x.x, A20[k],
                           __fmaf_rn(x.y, A21[k], __fmaf_rn(x.z, A22[k], b2[k])));
                float a3 = __fmaf_rn(x.x, A30[k],
                           __fmaf_rn(x.y, A31[k],
                           __fmaf_rn(x.z, A32[k], __fmaf_rn(x.w, A33[k], b3[k]))));
                qv[k] = __fmaf_rn(a0, a0,
                        __fmaf_rn(a1, a1,
                        __fmaf_rn(a2, a2, __fmaf_rn(a3, a3, nck[k]))));
            }
            float mn = fminf(fminf(fminf(qv[0], qv[1]), fminf(qv[2], qv[3])),
                             fminf(fminf(qv[4], qv[5]), fminf(qv[6], qv[7])));
            float ex[K_COMP];
            #pragma unroll
            for (int k = 0; k < K_COMP; k++) ex[k] = ex2f(mn - qv[k]);
            float s = ((ex[0] + ex[1]) + (ex[2] + ex[3])) +
                      ((ex[4] + ex[5]) + (ex[6] + ex[7]));
            float inv = rcpf(s);                       // s >= 1, safe
            #pragma unroll
            for (int k = 0; k < K_COMP; k++) acc[k] = __fmaf_rn(ex[k], inv, acc[k]);
        }

        // ---- block reduce (4 warps) ----
        #pragma unroll
        for (int k = 0; k < K_COMP; k++) {
            float v = acc[k];
            v += __shfl_down_sync(0xffffffffu, v, 16);
            v += __shfl_down_sync(0xffffffffu, v, 8);
            v += __shfl_down_sync(0xffffffffu, v, 4);
            v += __shfl_down_sync(0xffffffffu, v, 2);
            v += __shfl_down_sync(0xffffffffu, v, 1);
            if (lane == 0) sred[wid][k] = v;
        }
        __syncthreads();
        if (tid < K_COMP) {
            g_respT[q][tid][m] = sred[0][tid] + sred[1][tid] +
                                 sred[2][tid] + sred[3][tid];
        }
        // sred reads above happen before the next ticket's __syncthreads,
        // which orders them before any new sred writes.
    }

    grid_barrier(&g_bar1);

    // ===================== PHASE 2: standardization (blocks 0..79) ===========
    if (blockIdx.x < Z_COLS) {
        const int c = blockIdx.x;
        float v[4];
        if (c < 72) {
            const float* col = g_zT[c];
            #pragma unroll
            for (int j = 0; j < 4; j++) v[j] = col[tid + 128 * j];
        } else {
            const int k = c - 72;
            #pragma unroll
            for (int j = 0; j < 4; j++) {
                int r = tid + 128 * j;
                v[j] = (g_respT[0][k][r] + g_respT[1][k][r] +
                        g_respT[2][k][r] + g_respT[3][k][r]) * (1.0f / (float)B_PTS);
            }
        }

        __shared__ float nsh[4];
        __shared__ float n_mean, n_rstd;

        float s = (v[0] + v[1]) + (v[2] + v[3]);
        s += __shfl_down_sync(0xffffffffu, s, 16);
        s += __shfl_down_sync(0xffffffffu, s, 8);
        s += __shfl_down_sync(0xffffffffu, s, 4);
        s += __shfl_down_sync(0xffffffffu, s, 2);
        s += __shfl_down_sync(0xffffffffu, s, 1);
        if (lane == 0) nsh[wid] = s;
        __syncthreads();
        if (tid == 0) n_mean = (nsh[0] + nsh[1] + nsh[2] + nsh[3]) * (1.0f / (float)M_ROWS);
        __syncthreads();
        float mean = n_mean;

        float qsum = 0.f;
        #pragma unroll
        for (int j = 0; j < 4; j++) {
            v[j] -= mean;
            qsum = __fmaf_rn(v[j], v[j], qsum);
        }
        qsum += __shfl_down_sync(0xffffffffu, qsum, 16);
        qsum += __shfl_down_sync(0xffffffffu, qsum, 8);
        qsum += __shfl_down_sync(0xffffffffu, qsum, 4);
        qsum += __shfl_down_sync(0xffffffffu, qsum, 2);
        qsum += __shfl_down_sync(0xffffffffu, qsum, 1);
        __syncthreads();
        if (lane == 0) nsh[wid] = qsum;
        __syncthreads();
        if (tid == 0) {
            float var = (nsh[0] + nsh[1] + nsh[2] + nsh[3]) * (1.0f / (float)(M_ROWS - 1));
            n_rstd = 1.0f / fmaxf(sqrtf(var), 1e-6f);
        }
        __syncthreads();
        float rstd = n_rstd;
        #pragma unroll
        for (int j = 0; j < 4; j++) {
            int r = tid + 128 * j;
            out[r * Z_COLS + c] = v[j] * rstd;
        }
    }

    // ============== counter reset (state -> 0 for graph replay) ==============
    __syncthreads();
    if (tid == 0) {
        __threadfence();
        unsigned d = atomicAdd(&g_done, 1u);
        if (d == NBLK - 1) {
            g_ticket = 0u;
            g_bar0 = 0u;
            g_bar1 = 0u;
            g_done = 0u;
            __threadfence();
        }
    }
}

// ---------------------------------------------------------------------------
extern "C" void kernel_launch(void* const* d_in, const int* in_sizes, int n_in,
                              void* d_out, int out_size) {
    const float* phi = (const float*)d_in[0];
    const float4* X = (const float4*)d_in[1];
    float* out = (float*)d_out;

    gmm_all<<<NBLK, 128>>>(phi, X, out);
}

// round 16
// speedup vs baseline: 1.2142x; 1.0667x over previous
#include <cuda_runtime.h>
#include <math.h>

#define M_ROWS 512
#define K_COMP 8
#define B_PTS  4096
#define PHI_DIM 120
#define Z_COLS 80
#define LOG2PI_F 1.8378770664093453f
#define LOG2E_F  1.4426950408889634f

#define NBLK    444             // 148 SMs x 3 CTAs, residency via launch_bounds
#define NUNIT   16384           // 512 m x 32 chunks (128 points each)

// Scratch (device globals — no allocation allowed)
__device__ float g_zT[72][M_ROWS];            // z cols 0..71, column-major
__device__ float g_respP[2][K_COMP][M_ROWS];  // two partial slots per (k,m)
__device__ unsigned g_arrive, g_done;

__device__ __forceinline__ float ex2f(float x) {
    float r; asm("ex2.approx.f32 %0, %1;" : "=f"(r) : "f"(x)); return r;
}
__device__ __forceinline__ float rcpf(float x) {
    float r; asm("rcp.approx.f32 %0, %1;" : "=f"(r) : "f"(x)); return r;
}

// ---------------------------------------------------------------------------
// One persistent kernel: balanced unit ranges -> grid barrier -> fused norm.
// ---------------------------------------------------------------------------
__global__ void __launch_bounds__(128, 3) gmm_all(const float* __restrict__ phi,
                                                  const float4* __restrict__ X,
                                                  float* __restrict__ out) {
    const int tid = threadIdx.x;
    const unsigned lane = tid & 31;
    const unsigned wid = tid >> 5;

    __shared__ float sp[K_COMP][15];
    __shared__ float sred[4][K_COMP];

    // Balanced contiguous unit range for this block (36 or 37 units).
    const int u0 = (blockIdx.x * NUNIT) / NBLK;
    const int u1 = ((blockIdx.x + 1) * NUNIT) / NBLK;

    int u = u0;
    while (u < u1) {
        const int m = u >> 5;
        const int mEndUnit = (m + 1) * 32;
        const int segEnd = (u1 < mEndUnit) ? u1 : mEndUnit;  // units in this m
        const bool ownStart = (u == m * 32);
        const bool ownEnd = (segEnd == mEndUnit);

        // ---- prep: threads 0..7, one k each ----
        if (tid < K_COMP) {
            const int k = tid;
            const float* pm = phi + m * PHI_DIM;

            float mx = -INFINITY;
            #pragma unroll
            for (int j = 0; j < K_COMP; j++) mx = fmaxf(mx, pm[j]);
            float s = 0.f;
            #pragma unroll
            for (int j = 0; j < K_COMP; j++) s += __expf(pm[j] - mx);
            float pik = __expf(pm[k] - mx) / s;

            float mu0 = pm[8 + k * 4 + 0];
            float mu1 = pm[8 + k * 4 + 1];
            float mu2 = pm[8 + k * 4 + 2];
            float mu3 = pm[8 + k * 4 + 3];

            const float* lv = pm + 40 + k * 10;
            float L00 = lv[0], L10 = lv[1], L11 = lv[2], L20 = lv[3], L21 = lv[4];
            float L22 = lv[5], L30 = lv[6], L31 = lv[7], L32 = lv[8], L33 = lv[9];

            float G00 = 1.0f / L00, G11 = 1.0f / L11, G22 = 1.0f / L22, G33 = 1.0f / L33;
            float G10 = -L10 * G00 * G11;
            float G21 = -L21 * G11 * G22;
            float G20 = -(L20 * G00 + L21 * G10) * G22;
            float G32 = -L32 * G22 * G33;
            float G31 = -(L31 * G11 + L32 * G21) * G33;
            float G30 = -(L30 * G00 + L31 * G10 + L32 * G20) * G33;

            const float sc = sqrtf(0.5f * LOG2E_F);   // |a|^2 in log2 units
            float A00 = sc * G00, A10 = sc * G10, A11 = sc * G11;
            float A20 = sc * G20, A21 = sc * G21, A22 = sc * G22;
            float A30 = sc * G30, A31 = sc * G31, A32 = sc * G32, A33 = sc * G33;

            sp[k][0] = A00; sp[k][1] = A10; sp[k][2] = A11; sp[k][3] = A20;
            sp[k][4] = A21; sp[k][5] = A22; sp[k][6] = A30; sp[k][7] = A31;
            sp[k][8] = A32; sp[k][9] = A33;
            sp[k][10] = -(A00 * mu0);
            sp[k][11] = -(A10 * mu0 + A11 * mu1);
            sp[k][12] = -(A20 * mu0 + A21 * mu1 + A22 * mu2);
            sp[k][13] = -(A30 * mu0 + A31 * mu1 + A32 * mu2 + A33 * mu3);

            float log_det = 2.0f * (__logf(fmaxf(fabsf(L00), 1e-8f)) +
                                    __logf(fmaxf(fabsf(L11), 1e-8f)) +
                                    __logf(fmaxf(fabsf(L22), 1e-8f)) +
                                    __logf(fmaxf(fabsf(L33), 1e-8f)));
            float ckv = __logf(fmaxf(pik, 1e-8f)) - 0.5f * (4.0f * LOG2PI_F + log_det);
            sp[k][14] = -(ckv * LOG2E_F);             // nck2

            if (ownStart) {
                g_zT[k * 4 + 0][m] = mu0;
                g_zT[k * 4 + 1][m] = mu1;
                g_zT[k * 4 + 2][m] = mu2;
                g_zT[k * 4 + 3][m] = mu3;
                g_zT[32 + k * 4 + 0][m] = __logf(fmaxf(fabsf(L00), 1e-6f));
                g_zT[32 + k * 4 + 1][m] = __logf(fmaxf(fabsf(L11), 1e-6f));
                g_zT[32 + k * 4 + 2][m] = __logf(fmaxf(fabsf(L22), 1e-6f));
                g_zT[32 + k * 4 + 3][m] = __logf(fmaxf(fabsf(L33), 1e-6f));
                g_zT[64 + k][m] = pik;
            }
        }
        __syncthreads();

        // ---- cache params in registers (broadcast LDS) ----
        float A00[K_COMP], A10[K_COMP], A11[K_COMP], A20[K_COMP], A21[K_COMP];
        float A22[K_COMP], A30[K_COMP], A31[K_COMP], A32[K_COMP], A33[K_COMP];
        float b0[K_COMP], b1[K_COMP], b2[K_COMP], b3[K_COMP], nck[K_COMP];
        #pragma unroll
        for (int k = 0; k < K_COMP; k++) {
            A00[k] = sp[k][0]; A10[k] = sp[k][1]; A11[k] = sp[k][2];
            A20[k] = sp[k][3]; A21[k] = sp[k][4]; A22[k] = sp[k][5];
            A30[k] = sp[k][6]; A31[k] = sp[k][7]; A32[k] = sp[k][8]; A33[k] = sp[k][9];
            b0[k] = sp[k][10]; b1[k] = sp[k][11]; b2[k] = sp[k][12]; b3[k] = sp[k][13];
            nck[k] = sp[k][14];
        }

        float acc[K_COMP];
        #pragma unroll
        for (int k = 0; k < K_COMP; k++) acc[k] = 0.f;

        // ---- accumulate over chunks [u - 32m, segEnd - 32m) of this m ----
        int cc = u - m * 32;
        const int cLast = segEnd - m * 32;
        for (; cc < cLast; cc++) {
            float4 x = X[cc * 128 + tid];
            float qv[K_COMP];
            #pragma unroll
            for (int k = 0; k < K_COMP; k++) {
                float a0 = __fmaf_rn(x.x, A00[k], b0[k]);
                float a1 = __fmaf_rn(x.x, A10[k], __fmaf_rn(x.y, A11[k], b1[k]));
                float a2 = __fmaf_rn(x.x, A20[k],
                           __fmaf_rn(x.y, A21[k], __fmaf_rn(x.z, A22[k], b2[k])));
                float a3 = __fmaf_rn(x.x, A30[k],
                           __fmaf_rn(x.y, A31[k],
                           __fmaf_rn(x.z, A32[k], __fmaf_rn(x.w, A33[k], b3[k]))));
                qv[k] = __fmaf_rn(a0, a0,
                        __fmaf_rn(a1, a1,
                        __fmaf_rn(a2, a2, __fmaf_rn(a3, a3, nck[k]))));
            }
            float mn = fminf(fminf(fminf(qv[0], qv[1]), fminf(qv[2], qv[3])),
                             fminf(fminf(qv[4], qv[5]), fminf(qv[6], qv[7])));
            #pragma unroll
            for (int k = 0; k < K_COMP; k++) qv[k] = ex2f(mn - qv[k]);
            float s = ((qv[0] + qv[1]) + (qv[2] + qv[3])) +
                      ((qv[4] + qv[5]) + (qv[6] + qv[7]));
            float inv = rcpf(s);                       // s >= 1, safe
            #pragma unroll
            for (int k = 0; k < K_COMP; k++) acc[k] = __fmaf_rn(qv[k], inv, acc[k]);
        }

        // ---- block reduce (4 warps) ----
        #pragma unroll
        for (int k = 0; k < K_COMP; k++) {
            float v = acc[k];
            v += __shfl_down_sync(0xffffffffu, v, 16);
            v += __shfl_down_sync(0xffffffffu, v, 8);
            v += __shfl_down_sync(0xffffffffu, v, 4);
            v += __shfl_down_sync(0xffffffffu, v, 2);
            v += __shfl_down_sync(0xffffffffu, v, 1);
            if (lane == 0) sred[wid][k] = v;
        }
        __syncthreads();
        if (tid < K_COMP) {
            float v = sred[0][tid] + sred[1][tid] + sred[2][tid] + sred[3][tid];
            if (ownStart) {
                g_respP[0][tid][m] = v;
                // full owner: nobody else writes slot 1 for this m
                if (ownEnd) g_respP[1][tid][m] = 0.f;
            } else {
                g_respP[1][tid][m] = v;
            }
        }
        u = segEnd;
        // tid<8 write g_respP then run next prep; others wait at the post-prep
        // __syncthreads, so sp/sred reuse is ordered.
    }

    // ===================== grid barrier (all 444 resident) ====================
    __syncthreads();
    if (tid == 0) {
        __threadfence();
        atomicAdd(&g_arrive, 1u);
        volatile unsigned* p = &g_arrive;
        while (*p < NBLK) __nanosleep(64);
    }
    __syncthreads();
    __threadfence();

    // ===================== PHASE 2: standardization (blocks 0..79) ===========
    if (blockIdx.x < Z_COLS) {
        const int c = blockIdx.x;
        float v[4];
        if (c < 72) {
            const float* col = g_zT[c];
            #pragma unroll
            for (int j = 0; j < 4; j++) v[j] = col[tid + 128 * j];
        } else {
            const int k = c - 72;
            #pragma unroll
            for (int j = 0; j < 4; j++) {
                int r = tid + 128 * j;
                v[j] = (g_respP[0][k][r] + g_respP[1][k][r]) * (1.0f / (float)B_PTS);
            }
        }

        __shared__ float nsh[4];
        __shared__ float n_mean, n_rstd;

        float s = (v[0] + v[1]) + (v[2] + v[3]);
        s += __shfl_down_sync(0xffffffffu, s, 16);
        s += __shfl_down_sync(0xffffffffu, s, 8);
        s += __shfl_down_sync(0xffffffffu, s, 4);
        s += __shfl_down_sync(0xffffffffu, s, 2);
        s += __shfl_down_sync(0xffffffffu, s, 1);
        if (lane == 0) nsh[wid] = s;
        __syncthreads();
        if (tid == 0) n_mean = (nsh[0] + nsh[1] + nsh[2] + nsh[3]) * (1.0f / (float)M_ROWS);
        __syncthreads();
        float mean = n_mean;

        float qsum = 0.f;
        #pragma unroll
        for (int j = 0; j < 4; j++) {
            v[j] -= mean;
            qsum = __fmaf_rn(v[j], v[j], qsum);
        }
        qsum += __shfl_down_sync(0xffffffffu, qsum, 16);
        qsum += __shfl_down_sync(0xffffffffu, qsum, 8);
        qsum += __shfl_down_sync(0xffffffffu, qsum, 4);
        qsum += __shfl_down_sync(0xffffffffu, qsum, 2);
        qsum += __shfl_down_sync(0xffffffffu, qsum, 1);
        __syncthreads();
        if (lane == 0) nsh[wid] = qsum;
        __syncthreads();
        if (tid == 0) {
            float var = (nsh[0] + nsh[1] + nsh[2] + nsh[3]) * (1.0f / (float)(M_ROWS - 1));
            n_rstd = 1.0f / fmaxf(sqrtf(var), 1e-6f);
        }
        __syncthreads();
        float rstd = n_rstd;
        #pragma unroll
        for (int j = 0; j < 4; j++) {
            int r = tid + 128 * j;
            out[r * Z_COLS + c] = v[j] * rstd;
        }
    }

    // ============== counter reset (state -> 0 for graph replay) ==============
    __syncthreads();
    if (tid == 0) {
        __threadfence();
        unsigned d = atomicAdd(&g_done, 1u);
        if (d == NBLK - 1) {
            g_arrive = 0u;
            g_done = 0u;
            __threadfence();
        }
    }
}

// ---------------------------------------------------------------------------
extern "C" void kernel_launch(void* const* d_in, const int* in_sizes, int n_in,
                              void* d_out, int out_size) {
    const float* phi = (const float*)d_in[0];
    const float4* X = (const float4*)d_in[1];
    float* out = (float*)d_out;

    gmm_all<<<NBLK, 128>>>(phi, X, out);
}

// round 17
// speedup vs baseline: 1.3117x; 1.0803x over previous
#include <cuda_runtime.h>
#include <math.h>

#define M_ROWS 512
#define K_COMP 8
#define B_PTS  4096
#define PHI_DIM 120
#define Z_COLS 80
#define LOG2PI_F 1.8378770664093453f
#define LOG2E_F  1.4426950408889634f

#define NBLK    444             // 148 SMs x 3 CTAs, residency via launch_bounds
#define NUNIT   16384           // 512 m x 32 chunks (128 points each)

// Scratch (device globals — no allocation allowed)
__device__ float g_zT[72][M_ROWS];            // z cols 0..71, column-major
__device__ float g_respP[2][K_COMP][M_ROWS];  // two partial slots per (k,m)
__device__ unsigned g_arrive, g_done;

__device__ __forceinline__ float ex2f(float x) {
    float r; asm("ex2.approx.f32 %0, %1;" : "=f"(r) : "f"(x)); return r;
}
__device__ __forceinline__ float rcpf(float x) {
    float r; asm("rcp.approx.f32 %0, %1;" : "=f"(r) : "f"(x)); return r;
}

// ---------------------------------------------------------------------------
// One persistent kernel: balanced unit ranges -> grid barrier -> fused norm.
// ---------------------------------------------------------------------------
__global__ void __launch_bounds__(128, 3) gmm_all(const float* __restrict__ phi,
                                                  const float4* __restrict__ X,
                                                  float* __restrict__ out) {
    const int tid = threadIdx.x;
    const unsigned lane = tid & 31;
    const unsigned wid = tid >> 5;

    __shared__ float sp[K_COMP][15];
    __shared__ float sred[4][K_COMP];

    // Balanced contiguous unit range for this block (36 or 37 units).
    const int u0 = (blockIdx.x * NUNIT) / NBLK;
    const int u1 = ((blockIdx.x + 1) * NUNIT) / NBLK;

    int u = u0;
    while (u < u1) {
        const int m = u >> 5;
        const int mEndUnit = (m + 1) * 32;
        const int segEnd = (u1 < mEndUnit) ? u1 : mEndUnit;  // units in this m
        const bool ownStart = (u == m * 32);
        const bool ownEnd = (segEnd == mEndUnit);

        // ---- prep: threads 0..7, one k each ----
        if (tid < K_COMP) {
            const int k = tid;
            const float* pm = phi + m * PHI_DIM;

            float mx = -INFINITY;
            #pragma unroll
            for (int j = 0; j < K_COMP; j++) mx = fmaxf(mx, pm[j]);
            float s = 0.f;
            #pragma unroll
            for (int j = 0; j < K_COMP; j++) s += __expf(pm[j] - mx);
            float pik = __expf(pm[k] - mx) / s;

            float mu0 = pm[8 + k * 4 + 0];
            float mu1 = pm[8 + k * 4 + 1];
            float mu2 = pm[8 + k * 4 + 2];
            float mu3 = pm[8 + k * 4 + 3];

            const float* lv = pm + 40 + k * 10;
            float L00 = lv[0], L10 = lv[1], L11 = lv[2], L20 = lv[3], L21 = lv[4];
            float L22 = lv[5], L30 = lv[6], L31 = lv[7], L32 = lv[8], L33 = lv[9];

            float G00 = 1.0f / L00, G11 = 1.0f / L11, G22 = 1.0f / L22, G33 = 1.0f / L33;
            float G10 = -L10 * G00 * G11;
            float G21 = -L21 * G11 * G22;
            float G20 = -(L20 * G00 + L21 * G10) * G22;
            float G32 = -L32 * G22 * G33;
            float G31 = -(L31 * G11 + L32 * G21) * G33;
            float G30 = -(L30 * G00 + L31 * G10 + L32 * G20) * G33;

            const float sc = sqrtf(0.5f * LOG2E_F);   // |a|^2 in log2 units
            float A00 = sc * G00, A10 = sc * G10, A11 = sc * G11;
            float A20 = sc * G20, A21 = sc * G21, A22 = sc * G22;
            float A30 = sc * G30, A31 = sc * G31, A32 = sc * G32, A33 = sc * G33;

            sp[k][0] = A00; sp[k][1] = A10; sp[k][2] = A11; sp[k][3] = A20;
            sp[k][4] = A21; sp[k][5] = A22; sp[k][6] = A30; sp[k][7] = A31;
            sp[k][8] = A32; sp[k][9] = A33;
            sp[k][10] = -(A00 * mu0);
            sp[k][11] = -(A10 * mu0 + A11 * mu1);
            sp[k][12] = -(A20 * mu0 + A21 * mu1 + A22 * mu2);
            sp[k][13] = -(A30 * mu0 + A31 * mu1 + A32 * mu2 + A33 * mu3);

            float log_det = 2.0f * (__logf(fmaxf(fabsf(L00), 1e-8f)) +
                                    __logf(fmaxf(fabsf(L11), 1e-8f)) +
                                    __logf(fmaxf(fabsf(L22), 1e-8f)) +
                                    __logf(fmaxf(fabsf(L33), 1e-8f)));
            float ckv = __logf(fmaxf(pik, 1e-8f)) - 0.5f * (4.0f * LOG2PI_F + log_det);
            sp[k][14] = -(ckv * LOG2E_F);             // nck2

            if (ownStart) {
                g_zT[k * 4 + 0][m] = mu0;
                g_zT[k * 4 + 1][m] = mu1;
                g_zT[k * 4 + 2][m] = mu2;
                g_zT[k * 4 + 3][m] = mu3;
                g_zT[32 + k * 4 + 0][m] = __logf(fmaxf(fabsf(L00), 1e-6f));
                g_zT[32 + k * 4 + 1][m] = __logf(fmaxf(fabsf(L11), 1e-6f));
                g_zT[32 + k * 4 + 2][m] = __logf(fmaxf(fabsf(L22), 1e-6f));
                g_zT[32 + k * 4 + 3][m] = __logf(fmaxf(fabsf(L33), 1e-6f));
                g_zT[64 + k][m] = pik;
            }
        }
        __syncthreads();

        // ---- cache params in registers (broadcast LDS) ----
        float A00[K_COMP], A10[K_COMP], A11[K_COMP], A20[K_COMP], A21[K_COMP];
        float A22[K_COMP], A30[K_COMP], A31[K_COMP], A32[K_COMP], A33[K_COMP];
        float b0[K_COMP], b1[K_COMP], b2[K_COMP], b3[K_COMP], nck[K_COMP];
        #pragma unroll
        for (int k = 0; k < K_COMP; k++) {
            A00[k] = sp[k][0]; A10[k] = sp[k][1]; A11[k] = sp[k][2];
            A20[k] = sp[k][3]; A21[k] = sp[k][4]; A22[k] = sp[k][5];
            A30[k] = sp[k][6]; A31[k] = sp[k][7]; A32[k] = sp[k][8]; A33[k] = sp[k][9];
            b0[k] = sp[k][10]; b1[k] = sp[k][11]; b2[k] = sp[k][12]; b3[k] = sp[k][13];
            nck[k] = sp[k][14];
        }

        float acc[K_COMP];
        #pragma unroll
        for (int k = 0; k < K_COMP; k++) acc[k] = 0.f;

        // ---- accumulate over this m's chunk range, 2 points in flight ----
        int cc = u - m * 32;
        const int cLast = segEnd - m * 32;

        for (; cc + 2 <= cLast; cc += 2) {
            float4 xa = X[cc * 128 + tid];
            float4 xb = X[(cc + 1) * 128 + tid];
            float qa[K_COMP], qb[K_COMP];
            #pragma unroll
            for (int k = 0; k < K_COMP; k++) {
                float p0 = __fmaf_rn(xa.x, A00[k], b0[k]);
                float r0 = __fmaf_rn(xb.x, A00[k], b0[k]);
                float p1 = __fmaf_rn(xa.x, A10[k], __fmaf_rn(xa.y, A11[k], b1[k]));
                float r1 = __fmaf_rn(xb.x, A10[k], __fmaf_rn(xb.y, A11[k], b1[k]));
                float p2 = __fmaf_rn(xa.x, A20[k],
                           __fmaf_rn(xa.y, A21[k], __fmaf_rn(xa.z, A22[k], b2[k])));
                float r2 = __fmaf_rn(xb.x, A20[k],
                           __fmaf_rn(xb.y, A21[k], __fmaf_rn(xb.z, A22[k], b2[k])));
                float p3 = __fmaf_rn(xa.x, A30[k],
                           __fmaf_rn(xa.y, A31[k],
                           __fmaf_rn(xa.z, A32[k], __fmaf_rn(xa.w, A33[k], b3[k]))));
                float r3 = __fmaf_rn(xb.x, A30[k],
                           __fmaf_rn(xb.y, A31[k],
                           __fmaf_rn(xb.z, A32[k], __fmaf_rn(xb.w, A33[k], b3[k]))));
                qa[k] = __fmaf_rn(p0, p0,
                        __fmaf_rn(p1, p1,
                        __fmaf_rn(p2, p2, __fmaf_rn(p3, p3, nck[k]))));
                qb[k] = __fmaf_rn(r0, r0,
                        __fmaf_rn(r1, r1,
                        __fmaf_rn(r2, r2, __fmaf_rn(r3, r3, nck[k]))));
            }
            float mna = fminf(fminf(fminf(qa[0], qa[1]), fminf(qa[2], qa[3])),
                              fminf(fminf(qa[4], qa[5]), fminf(qa[6], qa[7])));
            float mnb = fminf(fminf(fminf(qb[0], qb[1]), fminf(qb[2], qb[3])),
                              fminf(fminf(qb[4], qb[5]), fminf(qb[6], qb[7])));
            #pragma unroll
            for (int k = 0; k < K_COMP; k++) {
                qa[k] = ex2f(mna - qa[k]);
                qb[k] = ex2f(mnb - qb[k]);
            }
            float sa = ((qa[0] + qa[1]) + (qa[2] + qa[3])) +
                       ((qa[4] + qa[5]) + (qa[6] + qa[7]));
            float sb = ((qb[0] + qb[1]) + (qb[2] + qb[3])) +
                       ((qb[4] + qb[5]) + (qb[6] + qb[7]));
            float ia = rcpf(sa);
            float ib = rcpf(sb);
            #pragma unroll
            for (int k = 0; k < K_COMP; k++) {
                acc[k] = __fmaf_rn(qa[k], ia, acc[k]);
                acc[k] = __fmaf_rn(qb[k], ib, acc[k]);
            }
        }
        // remainder (0 or 1 chunk)
        if (cc < cLast) {
            float4 x = X[cc * 128 + tid];
            float qv[K_COMP];
            #pragma unroll
            for (int k = 0; k < K_COMP; k++) {
                float a0 = __fmaf_rn(x.x, A00[k], b0[k]);
                float a1 = __fmaf_rn(x.x, A10[k], __fmaf_rn(x.y, A11[k], b1[k]));
                float a2 = __fmaf_rn(x.x, A20[k],
                           __fmaf_rn(x.y, A21[k], __fmaf_rn(x.z, A22[k], b2[k])));
                float a3 = __fmaf_rn(x.x, A30[k],
                           __fmaf_rn(x.y, A31[k],
                           __fmaf_rn(x.z, A32[k], __fmaf_rn(x.w, A33[k], b3[k]))));
                qv[k] = __fmaf_rn(a0, a0,
                        __fmaf_rn(a1, a1,
                        __fmaf_rn(a2, a2, __fmaf_rn(a3, a3, nck[k]))));
            }
            float mn = fminf(fminf(fminf(qv[0], qv[1]), fminf(qv[2], qv[3])),
                             fminf(fminf(qv[4], qv[5]), fminf(qv[6], qv[7])));
            #pragma unroll
            for (int k = 0; k < K_COMP; k++) qv[k] = ex2f(mn - qv[k]);
            float s = ((qv[0] + qv[1]) + (qv[2] + qv[3])) +
                      ((qv[4] + qv[5]) + (qv[6] + qv[7]));
            float inv = rcpf(s);
            #pragma unroll
            for (int k = 0; k < K_COMP; k++) acc[k] = __fmaf_rn(qv[k], inv, acc[k]);
        }

        // ---- block reduce (4 warps) ----
        #pragma unroll
        for (int k = 0; k < K_COMP; k++) {
            float v = acc[k];
            v += __shfl_down_sync(0xffffffffu, v, 16);
            v += __shfl_down_sync(0xffffffffu, v, 8);
            v += __shfl_down_sync(0xffffffffu, v, 4);
            v += __shfl_down_sync(0xffffffffu, v, 2);
            v += __shfl_down_sync(0xffffffffu, v, 1);
            if (lane == 0) sred[wid][k] = v;
        }
        __syncthreads();
        if (tid < K_COMP) {
            float v = sred[0][tid] + sred[1][tid] + sred[2][tid] + sred[3][tid];
            if (ownStart) {
                g_respP[0][tid][m] = v;
                if (ownEnd) g_respP[1][tid][m] = 0.f;
            } else {
                g_respP[1][tid][m] = v;
            }
        }
        u = segEnd;
    }

    // ===================== grid barrier (all 444 resident) ====================
    __syncthreads();
    if (tid == 0) {
        __threadfence();
        atomicAdd(&g_arrive, 1u);
        volatile unsigned* p = &g_arrive;
        while (*p < NBLK) __nanosleep(64);
    }
    __syncthreads();
    __threadfence();

    // ===================== PHASE 2: standardization (blocks 0..79) ===========
    if (blockIdx.x < Z_COLS) {
        const int c = blockIdx.x;
        float v[4];
        if (c < 72) {
            const float* col = g_zT[c];
            #pragma unroll
            for (int j = 0; j < 4; j++) v[j] = col[tid + 128 * j];
        } else {
            const int k = c - 72;
            #pragma unroll
            for (int j = 0; j < 4; j++) {
                int r = tid + 128 * j;
                v[j] = (g_respP[0][k][r] + g_respP[1][k][r]) * (1.0f / (float)B_PTS);
            }
        }

        __shared__ float nsh[4];
        __shared__ float n_mean, n_rstd;

        float s = (v[0] + v[1]) + (v[2] + v[3]);
        s += __shfl_down_sync(0xffffffffu, s, 16);
        s += __shfl_down_sync(0xffffffffu, s, 8);
        s += __shfl_down_sync(0xffffffffu, s, 4);
        s += __shfl_down_sync(0xffffffffu, s, 2);
        s += __shfl_down_sync(0xffffffffu, s, 1);
        if (lane == 0) nsh[wid] = s;
        __syncthreads();
        if (tid == 0) n_mean = (nsh[0] + nsh[1] + nsh[2] + nsh[3]) * (1.0f / (float)M_ROWS);
        __syncthreads();
        float mean = n_mean;

        float qsum = 0.f;
        #pragma unroll
        for (int j = 0; j < 4; j++) {
            v[j] -= mean;
            qsum = __fmaf_rn(v[j], v[j], qsum);
        }
        qsum += __shfl_down_sync(0xffffffffu, qsum, 16);
        qsum += __shfl_down_sync(0xffffffffu, qsum, 8);
        qsum += __shfl_down_sync(0xffffffffu, qsum, 4);
        qsum += __shfl_down_sync(0xffffffffu, qsum, 2);
        qsum += __shfl_down_sync(0xffffffffu, qsum, 1);
        __syncthreads();
        if (lane == 0) nsh[wid] = qsum;
        __syncthreads();
        if (tid == 0) {
            float var = (nsh[0] + nsh[1] + nsh[2] + nsh[3]) * (1.0f / (float)(M_ROWS - 1));
            n_rstd = 1.0f / fmaxf(sqrtf(var), 1e-6f);
        }
        __syncthreads();
        float rstd = n_rstd;
        #pragma unroll
        for (int j = 0; j < 4; j++) {
            int r = tid + 128 * j;
            out[r * Z_COLS + c] = v[j] * rstd;
        }
    }

    // ============== counter reset (state -> 0 for graph replay) ==============
    __syncthreads();
    if (tid == 0) {
        __threadfence();
        unsigned d = atomicAdd(&g_done, 1u);
        if (d == NBLK - 1) {
            g_arrive = 0u;
            g_done = 0u;
            __threadfence();
        }
    }
}

// ---------------------------------------------------------------------------
extern "C" void kernel_launch(void* const* d_in, const int* in_sizes, int n_in,
                              void* d_out, int out_size) {
    const float* phi = (const float*)d_in[0];
    const float4* X = (const float4*)d_in[1];
    float* out = (float*)d_out;

    gmm_all<<<NBLK, 128>>>(phi, X, out);
}